// round 10
// baseline (speedup 1.0000x reference)
#include <cuda_runtime.h>
#include <cuda_bf16.h>
#include <math.h>
#include <cstdint>

// Problem constants (fixed shapes)
#define B_SZ 4096
#define I_SZ 512
#define H_SZ 512
#define O_SZ 512
#define E_SZ 8
#define C_SZ 8          // GRID_SIZE + ORDER
#define KF   4608       // featurized K: 512 * 9
#define FSTRIDE ((size_t)B_SZ * KF)

// ---------------- scratch (device globals) ----------------
__device__ __nv_bfloat16 g_F1h[FSTRIDE];
__device__ __nv_bfloat16 g_F1l[FSTRIDE];
__device__ __nv_bfloat16 g_F2h[E_SZ * FSTRIDE];   // per-expert, gate-scaled
__device__ __nv_bfloat16 g_F2l[E_SZ * FSTRIDE];
__device__ __nv_bfloat16 g_W1h[(size_t)E_SZ * H_SZ * KF];
__device__ __nv_bfloat16 g_W1l[(size_t)E_SZ * H_SZ * KF];
__device__ __nv_bfloat16 g_W2h[(size_t)E_SZ * O_SZ * KF];
__device__ __nv_bfloat16 g_W2l[(size_t)E_SZ * O_SZ * KF];
__device__ float g_gate[(size_t)B_SZ * E_SZ];

// ---------------- PTX helpers (generic features only) ----------------
__device__ __forceinline__ uint32_t smem_u32(const void* p) {
    uint32_t a;
    asm("{ .reg .u64 t; cvta.to.shared.u64 t, %1; cvt.u32.u64 %0, t; }" : "=r"(a) : "l"(p));
    return a;
}
__device__ __forceinline__ void cp16(uint32_t dst, const void* src) {
    asm volatile("cp.async.cg.shared.global [%0], [%1], 16;" :: "r"(dst), "l"(src));
}
__device__ __forceinline__ void cp_commit() { asm volatile("cp.async.commit_group;"); }
template <int N> __device__ __forceinline__ void cp_wait() {
    asm volatile("cp.async.wait_group %0;" :: "n"(N));
}
__device__ __forceinline__ void ldm_x4(uint32_t* r, uint32_t addr) {
    asm volatile("ldmatrix.sync.aligned.m8n8.x4.shared.b16 {%0,%1,%2,%3}, [%4];"
                 : "=r"(r[0]), "=r"(r[1]), "=r"(r[2]), "=r"(r[3]) : "r"(addr));
}
__device__ __forceinline__ void mma_bf16(float* d, const uint32_t* a, const uint32_t* b) {
    asm volatile(
        "mma.sync.aligned.m16n8k16.row.col.f32.bf16.bf16.f32 "
        "{%0,%1,%2,%3}, {%4,%5,%6,%7}, {%8,%9}, {%0,%1,%2,%3};"
        : "+f"(d[0]), "+f"(d[1]), "+f"(d[2]), "+f"(d[3])
        : "r"(a[0]), "r"(a[1]), "r"(a[2]), "r"(a[3]), "r"(b[0]), "r"(b[1]));
}

// ---------------- KAN featurization ----------------
__device__ __forceinline__ void kan_feat(float x, float* __restrict__ out) {
    float t[12];
#pragma unroll
    for (int k = 0; k < 12; k++) t[k] = (float)(k - 3) * 0.4f - 1.0f;
    float b0[11];
#pragma unroll
    for (int k = 0; k < 11; k++) b0[k] = (x >= t[k] && x < t[k + 1]) ? 1.0f : 0.0f;
    float b1[10];
#pragma unroll
    for (int k = 0; k < 10; k++) {
        float dl = t[k + 1] - t[k], dr = t[k + 2] - t[k + 1];
        b1[k] = (x - t[k]) * (1.0f / dl) * b0[k] + (t[k + 2] - x) * (1.0f / dr) * b0[k + 1];
    }
    float b2[9];
#pragma unroll
    for (int k = 0; k < 9; k++) {
        float dl = t[k + 2] - t[k], dr = t[k + 3] - t[k + 1];
        b2[k] = (x - t[k]) * (1.0f / dl) * b1[k] + (t[k + 3] - x) * (1.0f / dr) * b1[k + 1];
    }
    float b3[8];
#pragma unroll
    for (int k = 0; k < 8; k++) {
        float dl = t[k + 3] - t[k], dr = t[k + 4] - t[k + 1];
        b3[k] = (x - t[k]) * (1.0f / dl) * b2[k] + (t[k + 4] - x) * (1.0f / dr) * b2[k + 1];
    }
    out[0] = x / (1.0f + expf(-x));
#pragma unroll
    for (int k = 0; k < 8; k++) out[1 + k] = b3[k];
}

// ---------------- gate softmax ----------------
__global__ void gate_kernel(const float* __restrict__ x, const float* __restrict__ gw,
                            const float* __restrict__ gb, float* __restrict__ gate) {
    int warp = (blockIdx.x * blockDim.x + threadIdx.x) >> 5;
    int lane = threadIdx.x & 31;
    if (warp >= B_SZ) return;
    const float* xr = x + (size_t)warp * I_SZ;
    float acc[E_SZ];
#pragma unroll
    for (int e = 0; e < E_SZ; e++) acc[e] = 0.f;
    for (int i = lane; i < I_SZ; i += 32) {
        float xv = xr[i];
#pragma unroll
        for (int e = 0; e < E_SZ; e++) acc[e] += xv * gw[e * I_SZ + i];
    }
#pragma unroll
    for (int e = 0; e < E_SZ; e++) {
#pragma unroll
        for (int o = 16; o > 0; o >>= 1) acc[e] += __shfl_xor_sync(0xffffffffu, acc[e], o);
    }
    if (lane == 0) {
        float mx = -1e30f;
#pragma unroll
        for (int e = 0; e < E_SZ; e++) { acc[e] += gb[e]; mx = fmaxf(mx, acc[e]); }
        float s = 0.f;
#pragma unroll
        for (int e = 0; e < E_SZ; e++) { acc[e] = expf(acc[e] - mx); s += acc[e]; }
        float inv = 1.0f / s;
#pragma unroll
        for (int e = 0; e < E_SZ; e++) gate[(size_t)warp * E_SZ + e] = acc[e] * inv;
    }
}

// ---------------- featurize x (smem-staged vectorized writes) ----------------
__global__ __launch_bounds__(256) void featbf_kernel(const float* __restrict__ in,
                                                     __nv_bfloat16* __restrict__ Fh,
                                                     __nv_bfloat16* __restrict__ Fl) {
    __shared__ __align__(16) unsigned short sh[256 * 9];
    __shared__ __align__(16) unsigned short sl[256 * 9];
    int tid = threadIdx.x;
    int idx = blockIdx.x * 256 + tid;
    float v[9];
    kan_feat(in[idx], v);
#pragma unroll
    for (int j = 0; j < 9; j++) {
        __nv_bfloat16 h = __float2bfloat16(v[j]);
        sh[tid * 9 + j] = __bfloat16_as_ushort(h);
        sl[tid * 9 + j] = __bfloat16_as_ushort(__float2bfloat16(v[j] - __bfloat162float(h)));
    }
    __syncthreads();
    const uint4* s4h = reinterpret_cast<const uint4*>(sh);
    const uint4* s4l = reinterpret_cast<const uint4*>(sl);
    uint4* gh = reinterpret_cast<uint4*>(Fh + (size_t)blockIdx.x * 2304);
    uint4* gl = reinterpret_cast<uint4*>(Fl + (size_t)blockIdx.x * 2304);
    for (int k = tid; k < 288; k += 256) {
        gh[k] = s4h[k];
        gl[k] = s4l[k];
    }
}

// ---------------- weight packing (smem-staged vectorized writes) ----------------
__global__ __launch_bounds__(256) void packbf_kernel(const float* __restrict__ bw,
                                                     const float* __restrict__ sw,
                                                     const float* __restrict__ sc,
                                                     __nv_bfloat16* __restrict__ Wh,
                                                     __nv_bfloat16* __restrict__ Wl) {
    __shared__ __align__(16) unsigned short sh[256 * 9];
    __shared__ __align__(16) unsigned short sl[256 * 9];
    int tid = threadIdx.x;
    int idx = blockIdx.x * 256 + tid; // (e*N + n)*IN + i
    float vals[9];
    vals[0] = bw[idx];
    float s = sc[idx];
    const float* sp = sw + (size_t)idx * C_SZ;
#pragma unroll
    for (int c = 0; c < C_SZ; c++) vals[1 + c] = sp[c] * s;
#pragma unroll
    for (int j = 0; j < 9; j++) {
        __nv_bfloat16 h = __float2bfloat16(vals[j]);
        sh[tid * 9 + j] = __bfloat16_as_ushort(h);
        sl[tid * 9 + j] = __bfloat16_as_ushort(__float2bfloat16(vals[j] - __bfloat162float(h)));
    }
    __syncthreads();
    const uint4* s4h = reinterpret_cast<const uint4*>(sh);
    const uint4* s4l = reinterpret_cast<const uint4*>(sl);
    uint4* gh = reinterpret_cast<uint4*>(Wh + (size_t)blockIdx.x * 2304);
    uint4* gl = reinterpret_cast<uint4*>(Wl + (size_t)blockIdx.x * 2304);
    for (int k = tid; k < 288; k += 256) {
        gh[k] = s4h[k];
        gl[k] = s4l[k];
    }
}

// ---------------- GEMM common (256 threads, 8 warps, 2x4 warp grid) ----------------
#define BM 128
#define BN 128
#define BK 64
#define NCHUNK (KF / BK)        // 72
#define PLANE_BYTES 16384       // 128 rows * 128 B
#define STAGE_BYTES (4 * PLANE_BYTES)
#define NSTAGE 3
#define GEMM_SMEM (NSTAGE * STAGE_BYTES)   // 196608
#define HS_STRIDE 130

// issue cp.async for ONE plane (4 x 16B per thread), no commit
__device__ __forceinline__ void load_plane(uint32_t sb, int stage_idx, int plane,
                                           const __nv_bfloat16* g, int k0, int tid) {
    uint32_t pb = sb + (uint32_t)stage_idx * STAGE_BYTES + (uint32_t)plane * PLANE_BYTES;
#pragma unroll
    for (int it = 0; it < 4; it++) {
        int idx = tid + it * 256;
        int r = idx >> 3;
        int kk = idx & 7;
        uint32_t off = (uint32_t)(r * 128 + kk * 16);
        cp16(pb + (off ^ ((off >> 3) & 0x70)),
             g + (size_t)r * KF + k0 + kk * 8);
    }
}

__device__ __forceinline__ void load_chunk4(uint32_t sb, int stage_idx,
                                            const __nv_bfloat16* pAh, const __nv_bfloat16* pAl,
                                            const __nv_bfloat16* pBh, const __nv_bfloat16* pBl,
                                            int k0, int tid) {
    load_plane(sb, stage_idx, 0, pAh, k0, tid);
    load_plane(sb, stage_idx, 1, pAl, k0, tid);
    load_plane(sb, stage_idx, 2, pBh, k0, tid);
    load_plane(sb, stage_idx, 3, pBl, k0, tid);
    cp_commit();
}

// warp tile 64(m) x 32(n); warp grid 2(m) x 4(n)
struct WarpCtx {
    uint32_t a_row[4], a_xor[4], a_kb;
    uint32_t b_row[2], b_xor[2], b_kb;
};

__device__ __forceinline__ void init_warp_ctx(WarpCtx& w, int warp_m, int warp_n, int lane) {
#pragma unroll
    for (int mt = 0; mt < 4; mt++) {
        int r = warp_m * 64 + mt * 16 + (lane & 15);
        w.a_row[mt] = (uint32_t)(r * 128);
        w.a_xor[mt] = (uint32_t)((r & 7) << 4);
    }
    w.a_kb = (uint32_t)((lane >> 4) << 4);
#pragma unroll
    for (int p = 0; p < 2; p++) {
        int r = warp_n * 32 + p * 16 + ((lane >> 4) << 3) + (lane & 7);
        w.b_row[p] = (uint32_t)(r * 128);
        w.b_xor[p] = (uint32_t)((r & 7) << 4);
    }
    w.b_kb = (uint32_t)(((lane >> 3) & 1) << 4);
}

// one chunk of MMA work, with one prefetch plane issued per kstep
// (pf_g[ks] == nullptr -> no prefetch)
__device__ __forceinline__ void chunk_mma_pf(const WarpCtx& w, uint32_t stage,
                                             float acc[4][4][4],
                                             uint32_t sb, int pf_stage,
                                             const __nv_bfloat16* const* pf_g,
                                             int pf_k0, int tid, bool pf) {
    uint32_t pAh = stage, pAl = stage + PLANE_BYTES;
    uint32_t pBh = stage + 2 * PLANE_BYTES, pBl = stage + 3 * PLANE_BYTES;
#pragma unroll
    for (int ks = 0; ks < 4; ks++) {
        uint32_t kb = (uint32_t)(ks * 32);
        uint32_t aH[4][4], aL[4][4], bH[4][2], bL[4][2];
#pragma unroll
        for (int mt = 0; mt < 4; mt++) {
            uint32_t off = w.a_row[mt] + ((kb + w.a_kb) ^ w.a_xor[mt]);
            ldm_x4(aH[mt], pAh + off);
            ldm_x4(aL[mt], pAl + off);
        }
#pragma unroll
        for (int p = 0; p < 2; p++) {
            uint32_t off = w.b_row[p] + ((kb + w.b_kb) ^ w.b_xor[p]);
            uint32_t r4[4];
            ldm_x4(r4, pBh + off);
            bH[2 * p][0] = r4[0]; bH[2 * p][1] = r4[1];
            bH[2 * p + 1][0] = r4[2]; bH[2 * p + 1][1] = r4[3];
            ldm_x4(r4, pBl + off);
            bL[2 * p][0] = r4[0]; bL[2 * p][1] = r4[1];
            bL[2 * p + 1][0] = r4[2]; bL[2 * p + 1][1] = r4[3];
        }
        // interleave: issue one plane of the (c+2) prefetch under MMA backpressure
        if (pf) load_plane(sb, pf_stage, ks, pf_g[ks], pf_k0, tid);
#pragma unroll
        for (int mt = 0; mt < 4; mt++)
#pragma unroll
            for (int nt = 0; nt < 4; nt++) {
                mma_bf16(acc[mt][nt], aH[mt], bH[nt]);
                mma_bf16(acc[mt][nt], aH[mt], bL[nt]);
                mma_bf16(acc[mt][nt], aL[mt], bH[nt]);
            }
    }
    if (pf) cp_commit();
}

// ---------------- GEMM1 (all experts, fused featurize+gate epilogue) ----------------
__global__ __launch_bounds__(256, 1) void kan_gemm1(
    const __nv_bfloat16* __restrict__ F1h, const __nv_bfloat16* __restrict__ F1l,
    const __nv_bfloat16* __restrict__ W1h, const __nv_bfloat16* __restrict__ W1l,
    __nv_bfloat16* __restrict__ F2h, __nv_bfloat16* __restrict__ F2l,
    const float* __restrict__ gate)
{
    extern __shared__ char smem[];
    uint32_t sb = smem_u32(smem);
    const int tid = threadIdx.x;
    const int wid = tid >> 5, lane = tid & 31;
    const int warp_m = wid & 1, warp_n = wid >> 1;
    const int bm = blockIdx.y * BM, bn = blockIdx.x * BN;
    const int e = blockIdx.z;

    const __nv_bfloat16* gp[4] = {
        F1h + (size_t)bm * KF, F1l + (size_t)bm * KF,
        W1h + (size_t)e * H_SZ * KF + (size_t)bn * KF,
        W1l + (size_t)e * H_SZ * KF + (size_t)bn * KF
    };

    WarpCtx w;
    init_warp_ctx(w, warp_m, warp_n, lane);

    float acc[4][4][4];
#pragma unroll
    for (int mt = 0; mt < 4; mt++)
#pragma unroll
        for (int nt = 0; nt < 4; nt++)
#pragma unroll
            for (int j = 0; j < 4; j++) acc[mt][nt][j] = 0.f;

    load_chunk4(sb, 0, gp[0], gp[1], gp[2], gp[3], 0, tid);
    load_chunk4(sb, 1, gp[0], gp[1], gp[2], gp[3], BK, tid);

    for (int c = 0; c < NCHUNK; c++) {
        if (c + 2 < NCHUNK) cp_wait<1>(); else cp_wait<0>();
        __syncthreads();
        bool pf = (c + 2 < NCHUNK);
        chunk_mma_pf(w, sb + (uint32_t)(c % NSTAGE) * STAGE_BYTES, acc,
                     sb, (c + 2) % NSTAGE, gp, (c + 2) * BK, tid, pf);
    }

    // ---- fused featurize + gate-scale epilogue ----
    __syncthreads();
    float* Hs = reinterpret_cast<float*>(smem);
    const int gn0 = warp_n * 32;
#pragma unroll
    for (int mt = 0; mt < 4; mt++) {
        int r0 = warp_m * 64 + mt * 16 + (lane >> 2);
        int r1 = r0 + 8;
#pragma unroll
        for (int nt = 0; nt < 4; nt++) {
            int cc = gn0 + nt * 8 + (lane & 3) * 2;
            Hs[r0 * HS_STRIDE + cc]     = acc[mt][nt][0];
            Hs[r0 * HS_STRIDE + cc + 1] = acc[mt][nt][1];
            Hs[r1 * HS_STRIDE + cc]     = acc[mt][nt][2];
            Hs[r1 * HS_STRIDE + cc + 1] = acc[mt][nt][3];
        }
    }
    __syncthreads();
    const int row = tid >> 1;
    const int half = tid & 1;
    const float* hrow = Hs + row * HS_STRIDE + half * 64;
    const float gv = gate[(size_t)(bm + row) * E_SZ + e];
    size_t gbase = (size_t)e * FSTRIDE + (size_t)(bm + row) * KF + ((size_t)bn + half * 64) * 9;
    uint4* gh = reinterpret_cast<uint4*>(F2h + gbase);
    uint4* gl = reinterpret_cast<uint4*>(F2l + gbase);
#pragma unroll
    for (int b = 0; b < 8; b++) {
        uint32_t hi32[36], lo32[36];
#pragma unroll
        for (int el = 0; el < 8; el++) {
            float f[9];
            kan_feat(hrow[b * 8 + el], f);
#pragma unroll
            for (int j = 0; j < 9; j++) {
                int p = el * 9 + j;
                float v = f[j] * gv;
                __nv_bfloat16 h = __float2bfloat16(v);
                uint32_t hb = (uint32_t)__bfloat16_as_ushort(h);
                uint32_t lb = (uint32_t)__bfloat16_as_ushort(
                    __float2bfloat16(v - __bfloat162float(h)));
                if ((p & 1) == 0) { hi32[p >> 1] = hb; lo32[p >> 1] = lb; }
                else { hi32[p >> 1] |= hb << 16; lo32[p >> 1] |= lb << 16; }
            }
        }
#pragma unroll
        for (int q = 0; q < 9; q++) {
            gh[b * 9 + q] = make_uint4(hi32[q * 4], hi32[q * 4 + 1],
                                       hi32[q * 4 + 2], hi32[q * 4 + 3]);
            gl[b * 9 + q] = make_uint4(lo32[q * 4], lo32[q * 4 + 1],
                                       lo32[q * 4 + 2], lo32[q * 4 + 3]);
        }
    }
}

// ---------------- GEMM2 (fused over all experts, K = 8*4608) ----------------
#define NCHUNK2 (E_SZ * NCHUNK)   // 576

__global__ __launch_bounds__(256, 1) void kan_gemm2(
    const __nv_bfloat16* __restrict__ F2h, const __nv_bfloat16* __restrict__ F2l,
    const __nv_bfloat16* __restrict__ W2h, const __nv_bfloat16* __restrict__ W2l,
    float* __restrict__ Cout)
{
    extern __shared__ char smem[];
    uint32_t sb = smem_u32(smem);
    const int tid = threadIdx.x;
    const int wid = tid >> 5, lane = tid & 31;
    const int warp_m = wid & 1, warp_n = wid >> 1;
    const int bm = blockIdx.y * BM, bn = blockIdx.x * BN;

    WarpCtx w;
    init_warp_ctx(w, warp_m, warp_n, lane);

    float acc[4][4][4];
#pragma unroll
    for (int mt = 0; mt < 4; mt++)
#pragma unroll
        for (int nt = 0; nt < 4; nt++)
#pragma unroll
            for (int j = 0; j < 4; j++) acc[mt][nt][j] = 0.f;

    // pointer set for a given chunk index
    const __nv_bfloat16* gp[4];
    auto set_ptrs = [&](int cc, int& k0) {
        int e = cc / NCHUNK;
        k0 = (cc - e * NCHUNK) * BK;
        gp[0] = F2h + (size_t)e * FSTRIDE + (size_t)bm * KF;
        gp[1] = F2l + (size_t)e * FSTRIDE + (size_t)bm * KF;
        gp[2] = W2h + (size_t)e * O_SZ * KF + (size_t)bn * KF;
        gp[3] = W2l + (size_t)e * O_SZ * KF + (size_t)bn * KF;
    };

    int k0;
    set_ptrs(0, k0);
    load_chunk4(sb, 0, gp[0], gp[1], gp[2], gp[3], k0, tid);
    set_ptrs(1, k0);
    load_chunk4(sb, 1, gp[0], gp[1], gp[2], gp[3], k0, tid);

    for (int c = 0; c < NCHUNK2; c++) {
        if (c + 2 < NCHUNK2) cp_wait<1>(); else cp_wait<0>();
        __syncthreads();
        bool pf = (c + 2 < NCHUNK2);
        int pk0 = 0;
        if (pf) set_ptrs(c + 2, pk0);
        chunk_mma_pf(w, sb + (uint32_t)(c % NSTAGE) * STAGE_BYTES, acc,
                     sb, (c + 2) % NSTAGE, gp, pk0, tid, pf);
    }

    // ---- plain store epilogue (gate already folded into F2) ----
#pragma unroll
    for (int mt = 0; mt < 4; mt++) {
        int r0 = bm + warp_m * 64 + mt * 16 + (lane >> 2);
        int r1 = r0 + 8;
#pragma unroll
        for (int nt = 0; nt < 4; nt++) {
            int cc = bn + warp_n * 32 + nt * 8 + (lane & 3) * 2;
            *reinterpret_cast<float2*>(Cout + (size_t)r0 * 512 + cc) =
                make_float2(acc[mt][nt][0], acc[mt][nt][1]);
            *reinterpret_cast<float2*>(Cout + (size_t)r1 * 512 + cc) =
                make_float2(acc[mt][nt][2], acc[mt][nt][3]);
        }
    }
}

// ---------------- launch ----------------
extern "C" void kernel_launch(void* const* d_in, const int* in_sizes, int n_in,
                              void* d_out, int out_size) {
    const float* x         = (const float*)d_in[0];
    const float* gate_w    = (const float*)d_in[1];
    const float* gate_b    = (const float*)d_in[2];
    const float* base_w1   = (const float*)d_in[3];
    const float* spline_w1 = (const float*)d_in[4];
    const float* scaler1   = (const float*)d_in[5];
    const float* base_w2   = (const float*)d_in[6];
    const float* spline_w2 = (const float*)d_in[7];
    const float* scaler2   = (const float*)d_in[8];
    float* out = (float*)d_out;

    __nv_bfloat16 *pF1h, *pF1l, *pF2h, *pF2l, *pW1h, *pW1l, *pW2h, *pW2l;
    float *pG;
    cudaGetSymbolAddress((void**)&pF1h, g_F1h);
    cudaGetSymbolAddress((void**)&pF1l, g_F1l);
    cudaGetSymbolAddress((void**)&pF2h, g_F2h);
    cudaGetSymbolAddress((void**)&pF2l, g_F2l);
    cudaGetSymbolAddress((void**)&pW1h, g_W1h);
    cudaGetSymbolAddress((void**)&pW1l, g_W1l);
    cudaGetSymbolAddress((void**)&pW2h, g_W2h);
    cudaGetSymbolAddress((void**)&pW2l, g_W2l);
    cudaGetSymbolAddress((void**)&pG, g_gate);

    cudaFuncSetAttribute(kan_gemm1, cudaFuncAttributeMaxDynamicSharedMemorySize, GEMM_SMEM);
    cudaFuncSetAttribute(kan_gemm2, cudaFuncAttributeMaxDynamicSharedMemorySize, GEMM_SMEM);

    // 1. gate softmax
    gate_kernel<<<(B_SZ * 32 + 255) / 256, 256>>>(x, gate_w, gate_b, pG);
    // 2. pack weights
    packbf_kernel<<<E_SZ * H_SZ * I_SZ / 256, 256>>>(base_w1, spline_w1, scaler1, pW1h, pW1l);
    packbf_kernel<<<E_SZ * O_SZ * H_SZ / 256, 256>>>(base_w2, spline_w2, scaler2, pW2h, pW2l);
    // 3. featurize x
    featbf_kernel<<<B_SZ * I_SZ / 256, 256>>>(x, pF1h, pF1l);
    // 4. all experts' layer-1 GEMM + featurize+gate epilogue (one launch, 1024 CTAs)
    dim3 g1(O_SZ / BN, B_SZ / BM, E_SZ); // (4, 32, 8)
    kan_gemm1<<<g1, 256, GEMM_SMEM>>>(pF1h, pF1l, pW1h, pW1l, pF2h, pF2l, pG);
    // 5. fused layer-2 GEMM over all experts (one launch, 128 CTAs)
    dim3 g2(O_SZ / BN, B_SZ / BM);       // (4, 32)
    kan_gemm2<<<g2, 256, GEMM_SMEM>>>(pF2h, pF2l, pW2h, pW2l, out);
}

// round 16
// speedup vs baseline: 1.0241x; 1.0241x over previous
#include <cuda_runtime.h>
#include <cuda_bf16.h>
#include <math.h>
#include <cstdint>

// Problem constants (fixed shapes)
#define B_SZ 4096
#define I_SZ 512
#define H_SZ 512
#define O_SZ 512
#define E_SZ 8
#define C_SZ 8          // GRID_SIZE + ORDER
#define KF   4608       // featurized K: 512 * 9
#define FSTRIDE ((size_t)B_SZ * KF)

// ---------------- scratch (device globals) ----------------
__device__ __nv_bfloat16 g_F1h[FSTRIDE];
__device__ __nv_bfloat16 g_F1l[FSTRIDE];
__device__ __nv_bfloat16 g_F2h[E_SZ * FSTRIDE];   // per-expert, gate-scaled
__device__ __nv_bfloat16 g_F2l[E_SZ * FSTRIDE];
__device__ __nv_bfloat16 g_W1h[(size_t)E_SZ * H_SZ * KF];
__device__ __nv_bfloat16 g_W1l[(size_t)E_SZ * H_SZ * KF];
__device__ __nv_bfloat16 g_W2h[(size_t)E_SZ * O_SZ * KF];
__device__ __nv_bfloat16 g_W2l[(size_t)E_SZ * O_SZ * KF];
__device__ float g_gate[(size_t)B_SZ * E_SZ];

// ---------------- PTX helpers (generic features only) ----------------
__device__ __forceinline__ uint32_t smem_u32(const void* p) {
    uint32_t a;
    asm("{ .reg .u64 t; cvta.to.shared.u64 t, %1; cvt.u32.u64 %0, t; }" : "=r"(a) : "l"(p));
    return a;
}
__device__ __forceinline__ void cp16(uint32_t dst, const void* src) {
    asm volatile("cp.async.cg.shared.global [%0], [%1], 16;" :: "r"(dst), "l"(src));
}
__device__ __forceinline__ void cp_commit() { asm volatile("cp.async.commit_group;"); }
template <int N> __device__ __forceinline__ void cp_wait() {
    asm volatile("cp.async.wait_group %0;" :: "n"(N));
}
__device__ __forceinline__ void ldm_x4(uint32_t* r, uint32_t addr) {
    asm volatile("ldmatrix.sync.aligned.m8n8.x4.shared.b16 {%0,%1,%2,%3}, [%4];"
                 : "=r"(r[0]), "=r"(r[1]), "=r"(r[2]), "=r"(r[3]) : "r"(addr));
}
__device__ __forceinline__ void mma_bf16(float* d, const uint32_t* a, const uint32_t* b) {
    asm volatile(
        "mma.sync.aligned.m16n8k16.row.col.f32.bf16.bf16.f32 "
        "{%0,%1,%2,%3}, {%4,%5,%6,%7}, {%8,%9}, {%0,%1,%2,%3};"
        : "+f"(d[0]), "+f"(d[1]), "+f"(d[2]), "+f"(d[3])
        : "r"(a[0]), "r"(a[1]), "r"(a[2]), "r"(a[3]), "r"(b[0]), "r"(b[1]));
}

// ---------------- KAN featurization ----------------
__device__ __forceinline__ void kan_feat(float x, float* __restrict__ out) {
    float t[12];
#pragma unroll
    for (int k = 0; k < 12; k++) t[k] = (float)(k - 3) * 0.4f - 1.0f;
    float b0[11];
#pragma unroll
    for (int k = 0; k < 11; k++) b0[k] = (x >= t[k] && x < t[k + 1]) ? 1.0f : 0.0f;
    float b1[10];
#pragma unroll
    for (int k = 0; k < 10; k++) {
        float dl = t[k + 1] - t[k], dr = t[k + 2] - t[k + 1];
        b1[k] = (x - t[k]) * (1.0f / dl) * b0[k] + (t[k + 2] - x) * (1.0f / dr) * b0[k + 1];
    }
    float b2[9];
#pragma unroll
    for (int k = 0; k < 9; k++) {
        float dl = t[k + 2] - t[k], dr = t[k + 3] - t[k + 1];
        b2[k] = (x - t[k]) * (1.0f / dl) * b1[k] + (t[k + 3] - x) * (1.0f / dr) * b1[k + 1];
    }
    float b3[8];
#pragma unroll
    for (int k = 0; k < 8; k++) {
        float dl = t[k + 3] - t[k], dr = t[k + 4] - t[k + 1];
        b3[k] = (x - t[k]) * (1.0f / dl) * b2[k] + (t[k + 4] - x) * (1.0f / dr) * b2[k + 1];
    }
    out[0] = x / (1.0f + expf(-x));
#pragma unroll
    for (int k = 0; k < 8; k++) out[1 + k] = b3[k];
}

// ---------------- gate softmax ----------------
__global__ void gate_kernel(const float* __restrict__ x, const float* __restrict__ gw,
                            const float* __restrict__ gb, float* __restrict__ gate) {
    int warp = (blockIdx.x * blockDim.x + threadIdx.x) >> 5;
    int lane = threadIdx.x & 31;
    if (warp >= B_SZ) return;
    const float* xr = x + (size_t)warp * I_SZ;
    float acc[E_SZ];
#pragma unroll
    for (int e = 0; e < E_SZ; e++) acc[e] = 0.f;
    for (int i = lane; i < I_SZ; i += 32) {
        float xv = xr[i];
#pragma unroll
        for (int e = 0; e < E_SZ; e++) acc[e] += xv * gw[e * I_SZ + i];
    }
#pragma unroll
    for (int e = 0; e < E_SZ; e++) {
#pragma unroll
        for (int o = 16; o > 0; o >>= 1) acc[e] += __shfl_xor_sync(0xffffffffu, acc[e], o);
    }
    if (lane == 0) {
        float mx = -1e30f;
#pragma unroll
        for (int e = 0; e < E_SZ; e++) { acc[e] += gb[e]; mx = fmaxf(mx, acc[e]); }
        float s = 0.f;
#pragma unroll
        for (int e = 0; e < E_SZ; e++) { acc[e] = expf(acc[e] - mx); s += acc[e]; }
        float inv = 1.0f / s;
#pragma unroll
        for (int e = 0; e < E_SZ; e++) gate[(size_t)warp * E_SZ + e] = acc[e] * inv;
    }
}

// ---------------- featurize x (smem-staged vectorized writes) ----------------
__global__ __launch_bounds__(256) void featbf_kernel(const float* __restrict__ in,
                                                     __nv_bfloat16* __restrict__ Fh,
                                                     __nv_bfloat16* __restrict__ Fl) {
    __shared__ __align__(16) unsigned short sh[256 * 9];
    __shared__ __align__(16) unsigned short sl[256 * 9];
    int tid = threadIdx.x;
    int idx = blockIdx.x * 256 + tid;
    float v[9];
    kan_feat(in[idx], v);
#pragma unroll
    for (int j = 0; j < 9; j++) {
        __nv_bfloat16 h = __float2bfloat16(v[j]);
        sh[tid * 9 + j] = __bfloat16_as_ushort(h);
        sl[tid * 9 + j] = __bfloat16_as_ushort(__float2bfloat16(v[j] - __bfloat162float(h)));
    }
    __syncthreads();
    const uint4* s4h = reinterpret_cast<const uint4*>(sh);
    const uint4* s4l = reinterpret_cast<const uint4*>(sl);
    uint4* gh = reinterpret_cast<uint4*>(Fh + (size_t)blockIdx.x * 2304);
    uint4* gl = reinterpret_cast<uint4*>(Fl + (size_t)blockIdx.x * 2304);
    for (int k = tid; k < 288; k += 256) {
        gh[k] = s4h[k];
        gl[k] = s4l[k];
    }
}

// ---------------- weight packing (smem-staged vectorized writes) ----------------
__global__ __launch_bounds__(256) void packbf_kernel(const float* __restrict__ bw,
                                                     const float* __restrict__ sw,
                                                     const float* __restrict__ sc,
                                                     __nv_bfloat16* __restrict__ Wh,
                                                     __nv_bfloat16* __restrict__ Wl) {
    __shared__ __align__(16) unsigned short sh[256 * 9];
    __shared__ __align__(16) unsigned short sl[256 * 9];
    int tid = threadIdx.x;
    int idx = blockIdx.x * 256 + tid; // (e*N + n)*IN + i
    float vals[9];
    vals[0] = bw[idx];
    float s = sc[idx];
    const float* sp = sw + (size_t)idx * C_SZ;
#pragma unroll
    for (int c = 0; c < C_SZ; c++) vals[1 + c] = sp[c] * s;
#pragma unroll
    for (int j = 0; j < 9; j++) {
        __nv_bfloat16 h = __float2bfloat16(vals[j]);
        sh[tid * 9 + j] = __bfloat16_as_ushort(h);
        sl[tid * 9 + j] = __bfloat16_as_ushort(__float2bfloat16(vals[j] - __bfloat162float(h)));
    }
    __syncthreads();
    const uint4* s4h = reinterpret_cast<const uint4*>(sh);
    const uint4* s4l = reinterpret_cast<const uint4*>(sl);
    uint4* gh = reinterpret_cast<uint4*>(Wh + (size_t)blockIdx.x * 2304);
    uint4* gl = reinterpret_cast<uint4*>(Wl + (size_t)blockIdx.x * 2304);
    for (int k = tid; k < 288; k += 256) {
        gh[k] = s4h[k];
        gl[k] = s4l[k];
    }
}

// ---------------- GEMM common ----------------
// 256 threads, 8 warps = 2(m) x 2(n) x 2(k); warp tile 64 x 64 x 32
#define BM 128
#define BN 128
#define BK 64
#define NCHUNK (KF / BK)        // 72
#define PLANE_BYTES 16384       // 128 rows * 128 B
#define STAGE_BYTES (4 * PLANE_BYTES)
#define NSTAGE 3
#define GEMM_SMEM (NSTAGE * STAGE_BYTES)   // 196608
#define HS_STRIDE 132           // floats; 132*4=528 B (16B-aligned rows)

__device__ __forceinline__ void load_chunk_ptrs(uint32_t sb, int stage_idx,
                                                const __nv_bfloat16* pA_h,
                                                const __nv_bfloat16* pA_l,
                                                const __nv_bfloat16* pB_h,
                                                const __nv_bfloat16* pB_l,
                                                int k0, int tid) {
    uint32_t base = sb + (uint32_t)stage_idx * STAGE_BYTES;
    const __nv_bfloat16* gp[4] = { pA_h, pA_l, pB_h, pB_l };
#pragma unroll
    for (int p = 0; p < 4; p++) {
        const __nv_bfloat16* g = gp[p];
        uint32_t pb = base + p * PLANE_BYTES;
#pragma unroll
        for (int it = 0; it < 4; it++) {
            int idx = tid + it * 256;
            int r = idx >> 3;
            int kk = idx & 7;
            uint32_t off = (uint32_t)(r * 128 + kk * 16);
            cp16(pb + (off ^ ((off >> 3) & 0x70)),
                 g + (size_t)r * KF + k0 + kk * 8);
        }
    }
    cp_commit();
}

struct WarpCtx {
    uint32_t a_row[4], a_xor[4], a_kb;
    uint32_t b_row[4], b_xor[4], b_kb;
    uint32_t kbase;   // byte offset of this warp's k-half within BK (0 or 64)
};

__device__ __forceinline__ void init_warp_ctx(WarpCtx& w, int warp_m, int warp_n,
                                              int warp_k, int lane) {
#pragma unroll
    for (int mt = 0; mt < 4; mt++) {
        int r = warp_m * 64 + mt * 16 + (lane & 15);
        w.a_row[mt] = (uint32_t)(r * 128);
        w.a_xor[mt] = (uint32_t)((r & 7) << 4);
    }
    w.a_kb = (uint32_t)((lane >> 4) << 4);
#pragma unroll
    for (int p = 0; p < 4; p++) {
        int r = warp_n * 64 + p * 16 + ((lane >> 4) << 3) + (lane & 7);
        w.b_row[p] = (uint32_t)(r * 128);
        w.b_xor[p] = (uint32_t)((r & 7) << 4);
    }
    w.b_kb = (uint32_t)(((lane >> 3) & 1) << 4);
    w.kbase = (uint32_t)(warp_k * 64);   // 32 k-elems = 64 bytes
}

// one chunk: warp covers 64x64 tile over its 32-k half (2 ksteps of 16)
__device__ __forceinline__ void chunk_mma(const WarpCtx& w, uint32_t stage,
                                          float acc[4][8][4]) {
    uint32_t pAh = stage, pAl = stage + PLANE_BYTES;
    uint32_t pBh = stage + 2 * PLANE_BYTES, pBl = stage + 3 * PLANE_BYTES;
#pragma unroll
    for (int ks = 0; ks < 2; ks++) {
        uint32_t kb = w.kbase + (uint32_t)(ks * 32);
        uint32_t aH[4][4], aL[4][4], bH[8][2], bL[8][2];
#pragma unroll
        for (int mt = 0; mt < 4; mt++) {
            uint32_t off = w.a_row[mt] + ((kb + w.a_kb) ^ w.a_xor[mt]);
            ldm_x4(aH[mt], pAh + off);
            ldm_x4(aL[mt], pAl + off);
        }
#pragma unroll
        for (int p = 0; p < 4; p++) {
            uint32_t off = w.b_row[p] + ((kb + w.b_kb) ^ w.b_xor[p]);
            uint32_t r4[4];
            ldm_x4(r4, pBh + off);
            bH[2 * p][0] = r4[0]; bH[2 * p][1] = r4[1];
            bH[2 * p + 1][0] = r4[2]; bH[2 * p + 1][1] = r4[3];
            ldm_x4(r4, pBl + off);
            bL[2 * p][0] = r4[0]; bL[2 * p][1] = r4[1];
            bL[2 * p + 1][0] = r4[2]; bL[2 * p + 1][1] = r4[3];
        }
#pragma unroll
        for (int mt = 0; mt < 4; mt++)
#pragma unroll
            for (int nt = 0; nt < 8; nt++) {
                mma_bf16(acc[mt][nt], aH[mt], bH[nt]);
                mma_bf16(acc[mt][nt], aH[mt], bL[nt]);
                mma_bf16(acc[mt][nt], aL[mt], bH[nt]);
            }
    }
}

// stage acc into Hs with k-pair reduction; leaves result in Hs[128][HS_STRIDE]
__device__ __forceinline__ void reduce_to_smem(float* Hs, float acc[4][8][4],
                                               int warp_m, int warp_n, int warp_k,
                                               int lane) {
    const int gn0 = warp_n * 64;
    if (warp_k == 0) {
#pragma unroll
        for (int mt = 0; mt < 4; mt++) {
            int r0 = warp_m * 64 + mt * 16 + (lane >> 2);
            int r1 = r0 + 8;
#pragma unroll
            for (int nt = 0; nt < 8; nt++) {
                int cc = gn0 + nt * 8 + (lane & 3) * 2;
                Hs[r0 * HS_STRIDE + cc]     = acc[mt][nt][0];
                Hs[r0 * HS_STRIDE + cc + 1] = acc[mt][nt][1];
                Hs[r1 * HS_STRIDE + cc]     = acc[mt][nt][2];
                Hs[r1 * HS_STRIDE + cc + 1] = acc[mt][nt][3];
            }
        }
    }
    __syncthreads();
    if (warp_k == 1) {
#pragma unroll
        for (int mt = 0; mt < 4; mt++) {
            int r0 = warp_m * 64 + mt * 16 + (lane >> 2);
            int r1 = r0 + 8;
#pragma unroll
            for (int nt = 0; nt < 8; nt++) {
                int cc = gn0 + nt * 8 + (lane & 3) * 2;
                Hs[r0 * HS_STRIDE + cc]     += acc[mt][nt][0];
                Hs[r0 * HS_STRIDE + cc + 1] += acc[mt][nt][1];
                Hs[r1 * HS_STRIDE + cc]     += acc[mt][nt][2];
                Hs[r1 * HS_STRIDE + cc + 1] += acc[mt][nt][3];
            }
        }
    }
    __syncthreads();
}

// ---------------- GEMM1 (all experts, fused featurize+gate epilogue) ----------------
__global__ __launch_bounds__(256, 1) void kan_gemm1(
    const __nv_bfloat16* __restrict__ F1h, const __nv_bfloat16* __restrict__ F1l,
    const __nv_bfloat16* __restrict__ W1h, const __nv_bfloat16* __restrict__ W1l,
    __nv_bfloat16* __restrict__ F2h, __nv_bfloat16* __restrict__ F2l,
    const float* __restrict__ gate)
{
    extern __shared__ char smem[];
    uint32_t sb = smem_u32(smem);
    const int tid = threadIdx.x;
    const int wid = tid >> 5, lane = tid & 31;
    const int warp_m = wid & 1, warp_n = (wid >> 1) & 1, warp_k = wid >> 2;
    const int bm = blockIdx.y * BM, bn = blockIdx.x * BN;
    const int e = blockIdx.z;

    const __nv_bfloat16* pAh = F1h + (size_t)bm * KF;
    const __nv_bfloat16* pAl = F1l + (size_t)bm * KF;
    const __nv_bfloat16* pBh = W1h + (size_t)e * H_SZ * KF + (size_t)bn * KF;
    const __nv_bfloat16* pBl = W1l + (size_t)e * H_SZ * KF + (size_t)bn * KF;

    WarpCtx w;
    init_warp_ctx(w, warp_m, warp_n, warp_k, lane);

    float acc[4][8][4];
#pragma unroll
    for (int mt = 0; mt < 4; mt++)
#pragma unroll
        for (int nt = 0; nt < 8; nt++)
#pragma unroll
            for (int j = 0; j < 4; j++) acc[mt][nt][j] = 0.f;

    load_chunk_ptrs(sb, 0, pAh, pAl, pBh, pBl, 0, tid);
    load_chunk_ptrs(sb, 1, pAh, pAl, pBh, pBl, BK, tid);

    for (int c = 0; c < NCHUNK; c++) {
        if (c + 2 < NCHUNK) cp_wait<1>(); else cp_wait<0>();
        __syncthreads();
        chunk_mma(w, sb + (uint32_t)(c % NSTAGE) * STAGE_BYTES, acc);
        if (c + 2 < NCHUNK)
            load_chunk_ptrs(sb, (c + 2) % NSTAGE, pAh, pAl, pBh, pBl, (c + 2) * BK, tid);
    }

    // ---- k-reduce into SMEM, then fused featurize + gate-scale epilogue ----
    __syncthreads();
    float* Hs = reinterpret_cast<float*>(smem);
    reduce_to_smem(Hs, acc, warp_m, warp_n, warp_k, lane);

    const int row = tid >> 1;
    const int half = tid & 1;
    const float* hrow = Hs + row * HS_STRIDE + half * 64;
    const float gv = gate[(size_t)(bm + row) * E_SZ + e];
    size_t gbase = (size_t)e * FSTRIDE + (size_t)(bm + row) * KF + ((size_t)bn + half * 64) * 9;
    uint4* gh = reinterpret_cast<uint4*>(F2h + gbase);
    uint4* gl = reinterpret_cast<uint4*>(F2l + gbase);
#pragma unroll
    for (int b = 0; b < 8; b++) {
        uint32_t hi32[36], lo32[36];
#pragma unroll
        for (int el = 0; el < 8; el++) {
            float f[9];
            kan_feat(hrow[b * 8 + el], f);
#pragma unroll
            for (int j = 0; j < 9; j++) {
                int p = el * 9 + j;
                float v = f[j] * gv;
                __nv_bfloat16 h = __float2bfloat16(v);
                uint32_t hb = (uint32_t)__bfloat16_as_ushort(h);
                uint32_t lb = (uint32_t)__bfloat16_as_ushort(
                    __float2bfloat16(v - __bfloat162float(h)));
                if ((p & 1) == 0) { hi32[p >> 1] = hb; lo32[p >> 1] = lb; }
                else { hi32[p >> 1] |= hb << 16; lo32[p >> 1] |= lb << 16; }
            }
        }
#pragma unroll
        for (int q = 0; q < 9; q++) {
            gh[b * 9 + q] = make_uint4(hi32[q * 4], hi32[q * 4 + 1],
                                       hi32[q * 4 + 2], hi32[q * 4 + 3]);
            gl[b * 9 + q] = make_uint4(lo32[q * 4], lo32[q * 4 + 1],
                                       lo32[q * 4 + 2], lo32[q * 4 + 3]);
        }
    }
}

// ---------------- GEMM2 (fused over all experts, K = 8*4608) ----------------
#define NCHUNK2 (E_SZ * NCHUNK)   // 576

__global__ __launch_bounds__(256, 1) void kan_gemm2(
    const __nv_bfloat16* __restrict__ F2h, const __nv_bfloat16* __restrict__ F2l,
    const __nv_bfloat16* __restrict__ W2h, const __nv_bfloat16* __restrict__ W2l,
    float* __restrict__ Cout)
{
    extern __shared__ char smem[];
    uint32_t sb = smem_u32(smem);
    const int tid = threadIdx.x;
    const int wid = tid >> 5, lane = tid & 31;
    const int warp_m = wid & 1, warp_n = (wid >> 1) & 1, warp_k = wid >> 2;
    const int bm = blockIdx.y * BM, bn = blockIdx.x * BN;

    WarpCtx w;
    init_warp_ctx(w, warp_m, warp_n, warp_k, lane);

    float acc[4][8][4];
#pragma unroll
    for (int mt = 0; mt < 4; mt++)
#pragma unroll
        for (int nt = 0; nt < 8; nt++)
#pragma unroll
            for (int j = 0; j < 4; j++) acc[mt][nt][j] = 0.f;

    auto prefetch = [&](int cc, int stage_idx) {
        int e = cc / NCHUNK;
        int k0 = (cc - e * NCHUNK) * BK;
        const __nv_bfloat16* pAh = F2h + (size_t)e * FSTRIDE + (size_t)bm * KF;
        const __nv_bfloat16* pAl = F2l + (size_t)e * FSTRIDE + (size_t)bm * KF;
        const __nv_bfloat16* pBh = W2h + (size_t)e * O_SZ * KF + (size_t)bn * KF;
        const __nv_bfloat16* pBl = W2l + (size_t)e * O_SZ * KF + (size_t)bn * KF;
        load_chunk_ptrs(sb, stage_idx, pAh, pAl, pBh, pBl, k0, tid);
    };

    prefetch(0, 0);
    prefetch(1, 1);

    for (int c = 0; c < NCHUNK2; c++) {
        if (c + 2 < NCHUNK2) cp_wait<1>(); else cp_wait<0>();
        __syncthreads();
        chunk_mma(w, sb + (uint32_t)(c % NSTAGE) * STAGE_BYTES, acc);
        if (c + 2 < NCHUNK2) prefetch(c + 2, (c + 2) % NSTAGE);
    }

    // ---- k-reduce into SMEM, then cooperative vectorized store ----
    __syncthreads();
    float* Hs = reinterpret_cast<float*>(smem);
    reduce_to_smem(Hs, acc, warp_m, warp_n, warp_k, lane);

    const int row = tid >> 1;
    const int half = tid & 1;
    const float4* src = reinterpret_cast<const float4*>(Hs + row * HS_STRIDE + half * 64);
    float4* dst = reinterpret_cast<float4*>(Cout + (size_t)(bm + row) * 512 + bn + half * 64);
#pragma unroll
    for (int i = 0; i < 16; i++) dst[i] = src[i];
}

// ---------------- launch ----------------
extern "C" void kernel_launch(void* const* d_in, const int* in_sizes, int n_in,
                              void* d_out, int out_size) {
    const float* x         = (const float*)d_in[0];
    const float* gate_w    = (const float*)d_in[1];
    const float* gate_b    = (const float*)d_in[2];
    const float* base_w1   = (const float*)d_in[3];
    const float* spline_w1 = (const float*)d_in[4];
    const float* scaler1   = (const float*)d_in[5];
    const float* base_w2   = (const float*)d_in[6];
    const float* spline_w2 = (const float*)d_in[7];
    const float* scaler2   = (const float*)d_in[8];
    float* out = (float*)d_out;

    __nv_bfloat16 *pF1h, *pF1l, *pF2h, *pF2l, *pW1h, *pW1l, *pW2h, *pW2l;
    float *pG;
    cudaGetSymbolAddress((void**)&pF1h, g_F1h);
    cudaGetSymbolAddress((void**)&pF1l, g_F1l);
    cudaGetSymbolAddress((void**)&pF2h, g_F2h);
    cudaGetSymbolAddress((void**)&pF2l, g_F2l);
    cudaGetSymbolAddress((void**)&pW1h, g_W1h);
    cudaGetSymbolAddress((void**)&pW1l, g_W1l);
    cudaGetSymbolAddress((void**)&pW2h, g_W2h);
    cudaGetSymbolAddress((void**)&pW2l, g_W2l);
    cudaGetSymbolAddress((void**)&pG, g_gate);

    cudaFuncSetAttribute(kan_gemm1, cudaFuncAttributeMaxDynamicSharedMemorySize, GEMM_SMEM);
    cudaFuncSetAttribute(kan_gemm2, cudaFuncAttributeMaxDynamicSharedMemorySize, GEMM_SMEM);

    // 1. gate softmax
    gate_kernel<<<(B_SZ * 32 + 255) / 256, 256>>>(x, gate_w, gate_b, pG);
    // 2. pack weights
    packbf_kernel<<<E_SZ * H_SZ * I_SZ / 256, 256>>>(base_w1, spline_w1, scaler1, pW1h, pW1l);
    packbf_kernel<<<E_SZ * O_SZ * H_SZ / 256, 256>>>(base_w2, spline_w2, scaler2, pW2h, pW2l);
    // 3. featurize x
    featbf_kernel<<<B_SZ * I_SZ / 256, 256>>>(x, pF1h, pF1l);
    // 4. all experts' layer-1 GEMM + featurize+gate epilogue (one launch, 1024 CTAs)
    dim3 g1(O_SZ / BN, B_SZ / BM, E_SZ); // (4, 32, 8)
    kan_gemm1<<<g1, 256, GEMM_SMEM>>>(pF1h, pF1l, pW1h, pW1l, pF2h, pF2l, pG);
    // 5. fused layer-2 GEMM over all experts (one launch, 128 CTAs)
    dim3 g2(O_SZ / BN, B_SZ / BM);       // (4, 32)
    kan_gemm2<<<g2, 256, GEMM_SMEM>>>(pF2h, pF2l, pW2h, pW2l, out);
}

// round 17
// speedup vs baseline: 1.0710x; 1.0458x over previous
#include <cuda_runtime.h>
#include <cuda_bf16.h>
#include <math.h>
#include <cstdint>

// Problem constants (fixed shapes)
#define B_SZ 4096
#define I_SZ 512
#define H_SZ 512
#define O_SZ 512
#define E_SZ 8
#define C_SZ 8          // GRID_SIZE + ORDER
#define KF   4608       // featurized K: 512 * 9
#define FSTRIDE ((size_t)B_SZ * KF)

// ---------------- scratch (device globals) ----------------
__device__ __nv_bfloat16 g_F1h[FSTRIDE];
__device__ __nv_bfloat16 g_F1l[FSTRIDE];
__device__ __nv_bfloat16 g_F2h[E_SZ * FSTRIDE];   // per-expert, gate-scaled
__device__ __nv_bfloat16 g_F2l[E_SZ * FSTRIDE];
__device__ __nv_bfloat16 g_W1h[(size_t)E_SZ * H_SZ * KF];
__device__ __nv_bfloat16 g_W1l[(size_t)E_SZ * H_SZ * KF];
__device__ __nv_bfloat16 g_W2h[(size_t)E_SZ * O_SZ * KF];
__device__ __nv_bfloat16 g_W2l[(size_t)E_SZ * O_SZ * KF];
__device__ float g_gate[(size_t)B_SZ * E_SZ];

// ---------------- PTX helpers (generic features only) ----------------
__device__ __forceinline__ uint32_t smem_u32(const void* p) {
    uint32_t a;
    asm("{ .reg .u64 t; cvta.to.shared.u64 t, %1; cvt.u32.u64 %0, t; }" : "=r"(a) : "l"(p));
    return a;
}
__device__ __forceinline__ void cp16(uint32_t dst, const void* src) {
    asm volatile("cp.async.cg.shared.global [%0], [%1], 16;" :: "r"(dst), "l"(src));
}
__device__ __forceinline__ void cp_commit() { asm volatile("cp.async.commit_group;"); }
template <int N> __device__ __forceinline__ void cp_wait() {
    asm volatile("cp.async.wait_group %0;" :: "n"(N));
}
__device__ __forceinline__ void ldm_x4(uint32_t* r, uint32_t addr) {
    asm volatile("ldmatrix.sync.aligned.m8n8.x4.shared.b16 {%0,%1,%2,%3}, [%4];"
                 : "=r"(r[0]), "=r"(r[1]), "=r"(r[2]), "=r"(r[3]) : "r"(addr));
}
__device__ __forceinline__ void mma_bf16(float* d, const uint32_t* a, const uint32_t* b) {
    asm volatile(
        "mma.sync.aligned.m16n8k16.row.col.f32.bf16.bf16.f32 "
        "{%0,%1,%2,%3}, {%4,%5,%6,%7}, {%8,%9}, {%0,%1,%2,%3};"
        : "+f"(d[0]), "+f"(d[1]), "+f"(d[2]), "+f"(d[3])
        : "r"(a[0]), "r"(a[1]), "r"(a[2]), "r"(a[3]), "r"(b[0]), "r"(b[1]));
}

// ---------------- KAN featurization ----------------
__device__ __forceinline__ void kan_feat(float x, float* __restrict__ out) {
    float t[12];
#pragma unroll
    for (int k = 0; k < 12; k++) t[k] = (float)(k - 3) * 0.4f - 1.0f;
    float b0[11];
#pragma unroll
    for (int k = 0; k < 11; k++) b0[k] = (x >= t[k] && x < t[k + 1]) ? 1.0f : 0.0f;
    float b1[10];
#pragma unroll
    for (int k = 0; k < 10; k++) {
        float dl = t[k + 1] - t[k], dr = t[k + 2] - t[k + 1];
        b1[k] = (x - t[k]) * (1.0f / dl) * b0[k] + (t[k + 2] - x) * (1.0f / dr) * b0[k + 1];
    }
    float b2[9];
#pragma unroll
    for (int k = 0; k < 9; k++) {
        float dl = t[k + 2] - t[k], dr = t[k + 3] - t[k + 1];
        b2[k] = (x - t[k]) * (1.0f / dl) * b1[k] + (t[k + 3] - x) * (1.0f / dr) * b1[k + 1];
    }
    float b3[8];
#pragma unroll
    for (int k = 0; k < 8; k++) {
        float dl = t[k + 3] - t[k], dr = t[k + 4] - t[k + 1];
        b3[k] = (x - t[k]) * (1.0f / dl) * b2[k] + (t[k + 4] - x) * (1.0f / dr) * b2[k + 1];
    }
    out[0] = x / (1.0f + expf(-x));
#pragma unroll
    for (int k = 0; k < 8; k++) out[1 + k] = b3[k];
}

// ---------------- gate softmax ----------------
__global__ void gate_kernel(const float* __restrict__ x, const float* __restrict__ gw,
                            const float* __restrict__ gb, float* __restrict__ gate) {
    int warp = (blockIdx.x * blockDim.x + threadIdx.x) >> 5;
    int lane = threadIdx.x & 31;
    if (warp >= B_SZ) return;
    const float* xr = x + (size_t)warp * I_SZ;
    float acc[E_SZ];
#pragma unroll
    for (int e = 0; e < E_SZ; e++) acc[e] = 0.f;
    for (int i = lane; i < I_SZ; i += 32) {
        float xv = xr[i];
#pragma unroll
        for (int e = 0; e < E_SZ; e++) acc[e] += xv * gw[e * I_SZ + i];
    }
#pragma unroll
    for (int e = 0; e < E_SZ; e++) {
#pragma unroll
        for (int o = 16; o > 0; o >>= 1) acc[e] += __shfl_xor_sync(0xffffffffu, acc[e], o);
    }
    if (lane == 0) {
        float mx = -1e30f;
#pragma unroll
        for (int e = 0; e < E_SZ; e++) { acc[e] += gb[e]; mx = fmaxf(mx, acc[e]); }
        float s = 0.f;
#pragma unroll
        for (int e = 0; e < E_SZ; e++) { acc[e] = expf(acc[e] - mx); s += acc[e]; }
        float inv = 1.0f / s;
#pragma unroll
        for (int e = 0; e < E_SZ; e++) gate[(size_t)warp * E_SZ + e] = acc[e] * inv;
    }
}

// ---------------- featurize x (smem-staged vectorized writes) ----------------
__global__ __launch_bounds__(256) void featbf_kernel(const float* __restrict__ in,
                                                     __nv_bfloat16* __restrict__ Fh,
                                                     __nv_bfloat16* __restrict__ Fl) {
    __shared__ __align__(16) unsigned short sh[256 * 9];
    __shared__ __align__(16) unsigned short sl[256 * 9];
    int tid = threadIdx.x;
    int idx = blockIdx.x * 256 + tid;
    float v[9];
    kan_feat(in[idx], v);
#pragma unroll
    for (int j = 0; j < 9; j++) {
        __nv_bfloat16 h = __float2bfloat16(v[j]);
        sh[tid * 9 + j] = __bfloat16_as_ushort(h);
        sl[tid * 9 + j] = __bfloat16_as_ushort(__float2bfloat16(v[j] - __bfloat162float(h)));
    }
    __syncthreads();
    const uint4* s4h = reinterpret_cast<const uint4*>(sh);
    const uint4* s4l = reinterpret_cast<const uint4*>(sl);
    uint4* gh = reinterpret_cast<uint4*>(Fh + (size_t)blockIdx.x * 2304);
    uint4* gl = reinterpret_cast<uint4*>(Fl + (size_t)blockIdx.x * 2304);
    for (int k = tid; k < 288; k += 256) {
        gh[k] = s4h[k];
        gl[k] = s4l[k];
    }
}

// ---------------- weight packing (float4 reads + smem-staged writes) ----------------
__global__ __launch_bounds__(256) void packbf_kernel(const float* __restrict__ bw,
                                                     const float* __restrict__ sw,
                                                     const float* __restrict__ sc,
                                                     __nv_bfloat16* __restrict__ Wh,
                                                     __nv_bfloat16* __restrict__ Wl) {
    __shared__ __align__(16) unsigned short sh[256 * 9];
    __shared__ __align__(16) unsigned short sl[256 * 9];
    int tid = threadIdx.x;
    int idx = blockIdx.x * 256 + tid; // (e*N + n)*IN + i
    float vals[9];
    vals[0] = bw[idx];
    float s = sc[idx];
    // spline row: 8 floats, 32B-aligned -> 2x LDG.128
    const float4* sp4 = reinterpret_cast<const float4*>(sw) + (size_t)idx * 2;
    float4 v0 = sp4[0], v1 = sp4[1];
    vals[1] = v0.x * s; vals[2] = v0.y * s; vals[3] = v0.z * s; vals[4] = v0.w * s;
    vals[5] = v1.x * s; vals[6] = v1.y * s; vals[7] = v1.z * s; vals[8] = v1.w * s;
#pragma unroll
    for (int j = 0; j < 9; j++) {
        __nv_bfloat16 h = __float2bfloat16(vals[j]);
        sh[tid * 9 + j] = __bfloat16_as_ushort(h);
        sl[tid * 9 + j] = __bfloat16_as_ushort(__float2bfloat16(vals[j] - __bfloat162float(h)));
    }
    __syncthreads();
    const uint4* s4h = reinterpret_cast<const uint4*>(sh);
    const uint4* s4l = reinterpret_cast<const uint4*>(sl);
    uint4* gh = reinterpret_cast<uint4*>(Wh + (size_t)blockIdx.x * 2304);
    uint4* gl = reinterpret_cast<uint4*>(Wl + (size_t)blockIdx.x * 2304);
    for (int k = tid; k < 288; k += 256) {
        gh[k] = s4h[k];
        gl[k] = s4l[k];
    }
}

// ---------------- GEMM common (256 threads, 8 warps, 2x4 warp grid) ----------------
#define BM 128
#define BN 128
#define BK 64
#define NCHUNK (KF / BK)        // 72
#define PLANE_BYTES 16384       // 128 rows * 128 B
#define STAGE_BYTES (4 * PLANE_BYTES)
#define NSTAGE 3
#define GEMM_SMEM (NSTAGE * STAGE_BYTES)   // 196608
#define HS_STRIDE 130

__device__ __forceinline__ void load_chunk_ptrs(uint32_t sb, int stage_idx,
                                                const __nv_bfloat16* pA_h,
                                                const __nv_bfloat16* pA_l,
                                                const __nv_bfloat16* pB_h,
                                                const __nv_bfloat16* pB_l,
                                                int k0, int tid) {
    uint32_t base = sb + (uint32_t)stage_idx * STAGE_BYTES;
    const __nv_bfloat16* gp[4] = { pA_h, pA_l, pB_h, pB_l };
#pragma unroll
    for (int p = 0; p < 4; p++) {
        const __nv_bfloat16* g = gp[p];
        uint32_t pb = base + p * PLANE_BYTES;
#pragma unroll
        for (int it = 0; it < 4; it++) {
            int idx = tid + it * 256;
            int r = idx >> 3;
            int kk = idx & 7;
            uint32_t off = (uint32_t)(r * 128 + kk * 16);
            cp16(pb + (off ^ ((off >> 3) & 0x70)),
                 g + (size_t)r * KF + k0 + kk * 8);
        }
    }
    cp_commit();
}

struct WarpCtx {
    uint32_t a_row[4], a_xor[4], a_kb;
    uint32_t b_row[2], b_xor[2], b_kb;
};

__device__ __forceinline__ void init_warp_ctx(WarpCtx& w, int warp_m, int warp_n, int lane) {
#pragma unroll
    for (int mt = 0; mt < 4; mt++) {
        int r = warp_m * 64 + mt * 16 + (lane & 15);
        w.a_row[mt] = (uint32_t)(r * 128);
        w.a_xor[mt] = (uint32_t)((r & 7) << 4);
    }
    w.a_kb = (uint32_t)((lane >> 4) << 4);
#pragma unroll
    for (int p = 0; p < 2; p++) {
        int r = warp_n * 32 + p * 16 + ((lane >> 4) << 3) + (lane & 7);
        w.b_row[p] = (uint32_t)(r * 128);
        w.b_xor[p] = (uint32_t)((r & 7) << 4);
    }
    w.b_kb = (uint32_t)(((lane >> 3) & 1) << 4);
}

__device__ __forceinline__ void chunk_mma(const WarpCtx& w, uint32_t stage,
                                          float acc[4][4][4]) {
    uint32_t pAh = stage, pAl = stage + PLANE_BYTES;
    uint32_t pBh = stage + 2 * PLANE_BYTES, pBl = stage + 3 * PLANE_BYTES;
#pragma unroll
    for (int ks = 0; ks < 4; ks++) {
        uint32_t kb = (uint32_t)(ks * 32);
        uint32_t aH[4][4], aL[4][4], bH[4][2], bL[4][2];
#pragma unroll
        for (int mt = 0; mt < 4; mt++) {
            uint32_t off = w.a_row[mt] + ((kb + w.a_kb) ^ w.a_xor[mt]);
            ldm_x4(aH[mt], pAh + off);
            ldm_x4(aL[mt], pAl + off);
        }
#pragma unroll
        for (int p = 0; p < 2; p++) {
            uint32_t off = w.b_row[p] + ((kb + w.b_kb) ^ w.b_xor[p]);
            uint32_t r4[4];
            ldm_x4(r4, pBh + off);
            bH[2 * p][0] = r4[0]; bH[2 * p][1] = r4[1];
            bH[2 * p + 1][0] = r4[2]; bH[2 * p + 1][1] = r4[3];
            ldm_x4(r4, pBl + off);
            bL[2 * p][0] = r4[0]; bL[2 * p][1] = r4[1];
            bL[2 * p + 1][0] = r4[2]; bL[2 * p + 1][1] = r4[3];
        }
#pragma unroll
        for (int mt = 0; mt < 4; mt++)
#pragma unroll
            for (int nt = 0; nt < 4; nt++) {
                mma_bf16(acc[mt][nt], aH[mt], bH[nt]);
                mma_bf16(acc[mt][nt], aH[mt], bL[nt]);
                mma_bf16(acc[mt][nt], aL[mt], bH[nt]);
            }
    }
}

// ---------------- GEMM1 (all experts, fused featurize+gate epilogue) ----------------
__global__ __launch_bounds__(256, 1) void kan_gemm1(
    const __nv_bfloat16* __restrict__ F1h, const __nv_bfloat16* __restrict__ F1l,
    const __nv_bfloat16* __restrict__ W1h, const __nv_bfloat16* __restrict__ W1l,
    __nv_bfloat16* __restrict__ F2h, __nv_bfloat16* __restrict__ F2l,
    const float* __restrict__ gate)
{
    extern __shared__ char smem[];
    uint32_t sb = smem_u32(smem);
    const int tid = threadIdx.x;
    const int wid = tid >> 5, lane = tid & 31;
    const int warp_m = wid & 1, warp_n = wid >> 1;
    const int bm = blockIdx.y * BM, bn = blockIdx.x * BN;
    const int e = blockIdx.z;

    const __nv_bfloat16* pAh = F1h + (size_t)bm * KF;
    const __nv_bfloat16* pAl = F1l + (size_t)bm * KF;
    const __nv_bfloat16* pBh = W1h + (size_t)e * H_SZ * KF + (size_t)bn * KF;
    const __nv_bfloat16* pBl = W1l + (size_t)e * H_SZ * KF + (size_t)bn * KF;

    WarpCtx w;
    init_warp_ctx(w, warp_m, warp_n, lane);

    float acc[4][4][4];
#pragma unroll
    for (int mt = 0; mt < 4; mt++)
#pragma unroll
        for (int nt = 0; nt < 4; nt++)
#pragma unroll
            for (int j = 0; j < 4; j++) acc[mt][nt][j] = 0.f;

    load_chunk_ptrs(sb, 0, pAh, pAl, pBh, pBl, 0, tid);
    load_chunk_ptrs(sb, 1, pAh, pAl, pBh, pBl, BK, tid);

    for (int c = 0; c < NCHUNK; c++) {
        if (c + 2 < NCHUNK) cp_wait<1>(); else cp_wait<0>();
        __syncthreads();
        chunk_mma(w, sb + (uint32_t)(c % NSTAGE) * STAGE_BYTES, acc);
        if (c + 2 < NCHUNK)
            load_chunk_ptrs(sb, (c + 2) % NSTAGE, pAh, pAl, pBh, pBl, (c + 2) * BK, tid);
    }

    // ---- fused featurize + gate-scale epilogue ----
    __syncthreads();
    float* Hs = reinterpret_cast<float*>(smem);
    const int gn0 = warp_n * 32;
#pragma unroll
    for (int mt = 0; mt < 4; mt++) {
        int r0 = warp_m * 64 + mt * 16 + (lane >> 2);
        int r1 = r0 + 8;
#pragma unroll
        for (int nt = 0; nt < 4; nt++) {
            int cc = gn0 + nt * 8 + (lane & 3) * 2;
            Hs[r0 * HS_STRIDE + cc]     = acc[mt][nt][0];
            Hs[r0 * HS_STRIDE + cc + 1] = acc[mt][nt][1];
            Hs[r1 * HS_STRIDE + cc]     = acc[mt][nt][2];
            Hs[r1 * HS_STRIDE + cc + 1] = acc[mt][nt][3];
        }
    }
    __syncthreads();
    const int row = tid >> 1;
    const int half = tid & 1;
    const float* hrow = Hs + row * HS_STRIDE + half * 64;
    const float gv = gate[(size_t)(bm + row) * E_SZ + e];
    size_t gbase = (size_t)e * FSTRIDE + (size_t)(bm + row) * KF + ((size_t)bn + half * 64) * 9;
    uint4* gh = reinterpret_cast<uint4*>(F2h + gbase);
    uint4* gl = reinterpret_cast<uint4*>(F2l + gbase);
#pragma unroll
    for (int b = 0; b < 8; b++) {
        uint32_t hi32[36], lo32[36];
#pragma unroll
        for (int el = 0; el < 8; el++) {
            float f[9];
            kan_feat(hrow[b * 8 + el], f);
#pragma unroll
            for (int j = 0; j < 9; j++) {
                int p = el * 9 + j;
                float v = f[j] * gv;
                __nv_bfloat16 h = __float2bfloat16(v);
                uint32_t hb = (uint32_t)__bfloat16_as_ushort(h);
                uint32_t lb = (uint32_t)__bfloat16_as_ushort(
                    __float2bfloat16(v - __bfloat162float(h)));
                if ((p & 1) == 0) { hi32[p >> 1] = hb; lo32[p >> 1] = lb; }
                else { hi32[p >> 1] |= hb << 16; lo32[p >> 1] |= lb << 16; }
            }
        }
#pragma unroll
        for (int q = 0; q < 9; q++) {
            gh[b * 9 + q] = make_uint4(hi32[q * 4], hi32[q * 4 + 1],
                                       hi32[q * 4 + 2], hi32[q * 4 + 3]);
            gl[b * 9 + q] = make_uint4(lo32[q * 4], lo32[q * 4 + 1],
                                       lo32[q * 4 + 2], lo32[q * 4 + 3]);
        }
    }
}

// ---------------- GEMM2 (fused over all experts, K = 8*4608) ----------------
#define NCHUNK2 (E_SZ * NCHUNK)   // 576

__global__ __launch_bounds__(256, 1) void kan_gemm2(
    const __nv_bfloat16* __restrict__ F2h, const __nv_bfloat16* __restrict__ F2l,
    const __nv_bfloat16* __restrict__ W2h, const __nv_bfloat16* __restrict__ W2l,
    float* __restrict__ Cout)
{
    extern __shared__ char smem[];
    uint32_t sb = smem_u32(smem);
    const int tid = threadIdx.x;
    const int wid = tid >> 5, lane = tid & 31;
    const int warp_m = wid & 1, warp_n = wid >> 1;
    const int bm = blockIdx.y * BM, bn = blockIdx.x * BN;

    WarpCtx w;
    init_warp_ctx(w, warp_m, warp_n, lane);

    float acc[4][4][4];
#pragma unroll
    for (int mt = 0; mt < 4; mt++)
#pragma unroll
        for (int nt = 0; nt < 4; nt++)
#pragma unroll
            for (int j = 0; j < 4; j++) acc[mt][nt][j] = 0.f;

    auto prefetch = [&](int cc, int stage_idx) {
        int e = cc / NCHUNK;
        int k0 = (cc - e * NCHUNK) * BK;
        const __nv_bfloat16* pAh = F2h + (size_t)e * FSTRIDE + (size_t)bm * KF;
        const __nv_bfloat16* pAl = F2l + (size_t)e * FSTRIDE + (size_t)bm * KF;
        const __nv_bfloat16* pBh = W2h + (size_t)e * O_SZ * KF + (size_t)bn * KF;
        const __nv_bfloat16* pBl = W2l + (size_t)e * O_SZ * KF + (size_t)bn * KF;
        load_chunk_ptrs(sb, stage_idx, pAh, pAl, pBh, pBl, k0, tid);
    };

    prefetch(0, 0);
    prefetch(1, 1);

    for (int c = 0; c < NCHUNK2; c++) {
        if (c + 2 < NCHUNK2) cp_wait<1>(); else cp_wait<0>();
        __syncthreads();
        chunk_mma(w, sb + (uint32_t)(c % NSTAGE) * STAGE_BYTES, acc);
        if (c + 2 < NCHUNK2) prefetch(c + 2, (c + 2) % NSTAGE);
    }

    // ---- plain store epilogue (gate already folded into F2) ----
#pragma unroll
    for (int mt = 0; mt < 4; mt++) {
        int r0 = bm + warp_m * 64 + mt * 16 + (lane >> 2);
        int r1 = r0 + 8;
#pragma unroll
        for (int nt = 0; nt < 4; nt++) {
            int cc = bn + warp_n * 32 + nt * 8 + (lane & 3) * 2;
            *reinterpret_cast<float2*>(Cout + (size_t)r0 * 512 + cc) =
                make_float2(acc[mt][nt][0], acc[mt][nt][1]);
            *reinterpret_cast<float2*>(Cout + (size_t)r1 * 512 + cc) =
                make_float2(acc[mt][nt][2], acc[mt][nt][3]);
        }
    }
}

// ---------------- launch ----------------
extern "C" void kernel_launch(void* const* d_in, const int* in_sizes, int n_in,
                              void* d_out, int out_size) {
    const float* x         = (const float*)d_in[0];
    const float* gate_w    = (const float*)d_in[1];
    const float* gate_b    = (const float*)d_in[2];
    const float* base_w1   = (const float*)d_in[3];
    const float* spline_w1 = (const float*)d_in[4];
    const float* scaler1   = (const float*)d_in[5];
    const float* base_w2   = (const float*)d_in[6];
    const float* spline_w2 = (const float*)d_in[7];
    const float* scaler2   = (const float*)d_in[8];
    float* out = (float*)d_out;

    __nv_bfloat16 *pF1h, *pF1l, *pF2h, *pF2l, *pW1h, *pW1l, *pW2h, *pW2l;
    float *pG;
    cudaGetSymbolAddress((void**)&pF1h, g_F1h);
    cudaGetSymbolAddress((void**)&pF1l, g_F1l);
    cudaGetSymbolAddress((void**)&pF2h, g_F2h);
    cudaGetSymbolAddress((void**)&pF2l, g_F2l);
    cudaGetSymbolAddress((void**)&pW1h, g_W1h);
    cudaGetSymbolAddress((void**)&pW1l, g_W1l);
    cudaGetSymbolAddress((void**)&pW2h, g_W2h);
    cudaGetSymbolAddress((void**)&pW2l, g_W2l);
    cudaGetSymbolAddress((void**)&pG, g_gate);

    static bool attr_set = false;
    if (!attr_set) {
        cudaFuncSetAttribute(kan_gemm1, cudaFuncAttributeMaxDynamicSharedMemorySize, GEMM_SMEM);
        cudaFuncSetAttribute(kan_gemm2, cudaFuncAttributeMaxDynamicSharedMemorySize, GEMM_SMEM);
        attr_set = true;
    }

    // 1. gate softmax
    gate_kernel<<<(B_SZ * 32 + 255) / 256, 256>>>(x, gate_w, gate_b, pG);
    // 2. pack weights
    packbf_kernel<<<E_SZ * H_SZ * I_SZ / 256, 256>>>(base_w1, spline_w1, scaler1, pW1h, pW1l);
    packbf_kernel<<<E_SZ * O_SZ * H_SZ / 256, 256>>>(base_w2, spline_w2, scaler2, pW2h, pW2l);
    // 3. featurize x
    featbf_kernel<<<B_SZ * I_SZ / 256, 256>>>(x, pF1h, pF1l);
    // 4. all experts' layer-1 GEMM + featurize+gate epilogue (one launch, 1024 CTAs)
    dim3 g1(O_SZ / BN, B_SZ / BM, E_SZ); // (4, 32, 8)
    kan_gemm1<<<g1, 256, GEMM_SMEM>>>(pF1h, pF1l, pW1h, pW1l, pF2h, pF2l, pG);
    // 5. fused layer-2 GEMM over all experts (one launch, 128 CTAs)
    dim3 g2(O_SZ / BN, B_SZ / BM);       // (4, 32)
    kan_gemm2<<<g2, 256, GEMM_SMEM>>>(pF2h, pF2l, pW2h, pW2l, out);
}